// round 5
// baseline (speedup 1.0000x reference)
#include <cuda_runtime.h>
#include <math.h>
#include <stdint.h>

#define NN 128
#define DD 2048
#define EPSF 1e-12f
#define MARGINF 0.3f
#define KCHUNK 64        // K per GEMM block
#define KP 32            // k-pairs per chunk
#define NKCH 32          // number of K chunks (32*64 = 2048)
#define NBLK 128         // one block per SM, all co-resident
#define S2 66            // smem row stride in float2 (528B, 16B-aligned)

// ---------------- device scratch (no allocations allowed) ----------------
// partials: g_part[i][kc][j]
__device__ float g_part[NN * NKCH * NN];   // 2 MB
__device__ float g_norm[2 * NN];
__device__ float g_dist_ap[NN];
__device__ int   g_sel1[NN];
__device__ int   g_sel2[NN];
__device__ float g_trip[NN];
__device__ int   g_c0, g_c1, g_c2;         // phase barriers (zero-init, self-reset)

// packed f32x2 FMA: acc.{lo,hi} += a.{lo,hi} * b.{lo,hi}
__device__ __forceinline__ void ffma2(unsigned long long& acc,
                                      unsigned long long a, unsigned long long b) {
    asm("fma.rn.f32x2 %0, %1, %2, %0;" : "+l"(acc) : "l"(a), "l"(b));
}
__device__ __forceinline__ float2 up2(unsigned long long v) {
    float2 r;
    asm("mov.b64 {%0, %1}, %2;" : "=f"(r.x), "=f"(r.y) : "l"(v));
    return r;
}

// grid-wide spin barrier: all NBLK blocks resident by construction
__device__ __forceinline__ void gbar(int* c) {
    __threadfence();
    __syncthreads();
    if (threadIdx.x == 0) {
        atomicAdd(c, 1);
        while (*(volatile int*)c != NBLK) {}
    }
    __syncthreads();
    __threadfence();
}

__global__ void __launch_bounds__(512, 1)
k_fused(const float* __restrict__ f1, const float* __restrict__ f2,
        const int* __restrict__ tgt, float* __restrict__ out, int out_size) {
    const int tid = threadIdx.x;
    const int bid = blockIdx.x;

    __shared__ float2 As2[KP][S2];   // As2[kp][row] = (A[2kp],A[2kp+1]) of row
    __shared__ float2 Bs2[KP][S2];
    __shared__ int    st[NN];
    __shared__ float  s_dot[4][NN];
    __shared__ float  nred[16];
    __shared__ float  s_ap[4];
    __shared__ unsigned long long s_k1[4], s_k2[4];
    __shared__ float  red[16][2];
    __shared__ int    s_last;

    // ================= Phase A: split-K GEMM + folded norms ================
    const int quad = bid >> 5;              // 0..3
    const int kc = bid & 31;                // K chunk
    const int i0 = (quad & 1) * 64;
    const int j0 = (quad >> 1) * 64;
    const int k0 = kc * KCHUNK;

    // --- issue all global loads up front (GEMM tiles + this block's 2 norm rows)
    float4 va[2], vb[2];
    int rw[2], k4[2];
    #pragma unroll
    for (int s = 0; s < 2; s++) {
        const int idx = tid + 512 * s;      // 0..1023
        rw[s] = idx >> 4;                   // 0..63
        k4[s] = idx & 15;
        va[s] = *(const float4*)(f1 + (size_t)(i0 + rw[s]) * DD + k0 + k4[s] * 4);
        vb[s] = *(const float4*)(f2 + (size_t)(j0 + rw[s]) * DD + k0 + k4[s] * 4);
    }
    const int nrow = 2 * bid + (tid >> 8);  // this block handles rows 2b, 2b+1
    const float4* nbase = (const float4*)((nrow < NN) ? (f1 + (size_t)nrow * DD)
                                                      : (f2 + (size_t)(nrow - NN) * DD));
    const int npos = (tid & 255) * 2;
    float4 n0 = nbase[npos], n1 = nbase[npos + 1];

    // --- stage GEMM tiles k-pair interleaved
    #pragma unroll
    for (int s = 0; s < 2; s++) {
        As2[2 * k4[s] + 0][rw[s]] = make_float2(va[s].x, va[s].y);
        As2[2 * k4[s] + 1][rw[s]] = make_float2(va[s].z, va[s].w);
        Bs2[2 * k4[s] + 0][rw[s]] = make_float2(vb[s].x, vb[s].y);
        Bs2[2 * k4[s] + 1][rw[s]] = make_float2(vb[s].z, vb[s].w);
    }
    __syncthreads();

    // --- 2(i) x 4(j) register tile, fully unrolled k-pair loop
    const int ty2 = (tid >> 4) * 2;         // 2 rows
    const int tx4 = (tid & 15) * 4;         // 4 cols

    unsigned long long acc[2][4];
    #pragma unroll
    for (int m = 0; m < 2; m++)
        #pragma unroll
        for (int n = 0; n < 4; n++) acc[m][n] = 0ull;

    #pragma unroll
    for (int kp = 0; kp < KP; kp++) {
        ulonglong2 A2 = *(const ulonglong2*)&As2[kp][ty2];
        ulonglong2 B0 = *(const ulonglong2*)&Bs2[kp][tx4];
        ulonglong2 B1 = *(const ulonglong2*)&Bs2[kp][tx4 + 2];
        ffma2(acc[0][0], A2.x, B0.x); ffma2(acc[0][1], A2.x, B0.y);
        ffma2(acc[0][2], A2.x, B1.x); ffma2(acc[0][3], A2.x, B1.y);
        ffma2(acc[1][0], A2.y, B0.x); ffma2(acc[1][1], A2.y, B0.y);
        ffma2(acc[1][2], A2.y, B1.x); ffma2(acc[1][3], A2.y, B1.y);
    }

    #pragma unroll
    for (int m = 0; m < 2; m++) {
        float v[4];
        #pragma unroll
        for (int n = 0; n < 4; n++) {
            float2 p = up2(acc[m][n]);
            v[n] = p.x + p.y;
        }
        float4 o = make_float4(v[0], v[1], v[2], v[3]);
        *(float4*)&g_part[((size_t)(i0 + ty2 + m) * NKCH + kc) * NN + j0 + tx4] = o;
    }

    // --- norms: reduce the 2 rows (8 squares per thread already in regs)
    {
        float s = n0.x * n0.x + n0.y * n0.y + n0.z * n0.z + n0.w * n0.w
                + n1.x * n1.x + n1.y * n1.y + n1.z * n1.z + n1.w * n1.w;
        #pragma unroll
        for (int o = 16; o; o >>= 1) s += __shfl_xor_sync(0xffffffffu, s, o);
        if ((tid & 31) == 0) nred[tid >> 5] = s;
    }
    if (tid < NN) st[tid] = tgt[tid];
    __syncthreads();
    if (tid == 0) {
        float s = 0.f;
        #pragma unroll
        for (int q = 0; q < 8; q++) s += nred[q];
        g_norm[2 * bid] = s;
    } else if (tid == 256) {
        float s = 0.f;
        #pragma unroll
        for (int q = 8; q < 16; q++) s += nred[q];
        g_norm[2 * bid + 1] = s;
    }

    // --- precompute rank / pos mask for phase B (depends only on tgt)
    int ti = 0, rank = 0;
    bool pos = false;
    if (tid < NN) {
        ti = st[bid];
        pos = (st[tid] == ti);
        #pragma unroll 8
        for (int q = 0; q < NN; q++)
            rank += (q < tid && st[q] != ti) ? 1 : 0;
    }

    gbar(&g_c0);

    // ================= Phase B: distances + hard-example selection ========
    {
        const int i = bid;
        const int j = tid & 127;
        const int kh = tid >> 7;            // 4 K-quarters (8 chunks each)

        const float* pp = g_part + ((size_t)i * NKCH + kh * 8) * NN + j;
        float a0 = 0.f, a1 = 0.f;
        #pragma unroll
        for (int c = 0; c < 8; c += 2) {
            a0 += __ldcg(pp + (size_t)(c + 0) * NN);
            a1 += __ldcg(pp + (size_t)(c + 1) * NN);
        }
        s_dot[kh][j] = a0 + a1;
        __syncthreads();

        if (tid < NN) {
            float dot = (s_dot[0][j] + s_dot[1][j]) + (s_dot[2][j] + s_dot[3][j]);
            float d2 = __ldcg(&g_norm[i]) + __ldcg(&g_norm[NN + j]) - 2.f * dot;
            float d = sqrtf(fmaxf(d2, EPSF));

            float apv = pos ? d : -INFINITY;
            // (distance, column) lexicographic key: min == argmin with
            // first-occurrence tie-break (d > 0 so float bits order-preserve)
            unsigned long long key =
                ((unsigned long long)__float_as_uint(d) << 32) | (unsigned)j;
            unsigned long long k1 = (!pos && rank < 56) ? key : ~0ull;
            unsigned long long k2 = (!pos && rank >= 56 && rank < 112) ? key : ~0ull;

            #pragma unroll
            for (int o = 16; o; o >>= 1) {
                apv = fmaxf(apv, __shfl_xor_sync(0xffffffffu, apv, o));
                unsigned long long t1 = __shfl_xor_sync(0xffffffffu, k1, o);
                unsigned long long t2 = __shfl_xor_sync(0xffffffffu, k2, o);
                k1 = (t1 < k1) ? t1 : k1;
                k2 = (t2 < k2) ? t2 : k2;
            }
            const int w = j >> 5;
            if ((j & 31) == 0) { s_ap[w] = apv; s_k1[w] = k1; s_k2[w] = k2; }
        }
        __syncthreads();
        if (tid == 0) {
            float ap = s_ap[0];
            unsigned long long m1 = s_k1[0], m2 = s_k2[0];
            #pragma unroll
            for (int q = 1; q < 4; q++) {
                ap = fmaxf(ap, s_ap[q]);
                if (s_k1[q] < m1) m1 = s_k1[q];
                if (s_k2[q] < m2) m2 = s_k2[q];
            }
            g_dist_ap[i] = ap;
            g_sel1[i] = (int)(m1 & 0xffffffffull);
            g_sel2[i] = (int)(m2 & 0xffffffffull);
        }
    }

    gbar(&g_c1);

    // ================= Phase C: dist_an + triplet ==========================
    {
        const int k = bid;
        // feat_rgb_mid / feat_ir_mid index shuffle; anchor is always f1[k]
        int m = (k < 32) ? k : (k < 64) ? (k + 32) : (k < 96) ? (k - 32) : k;
        const int a = __ldcg(&g_sel1[m]);
        const int b = __ldcg(&g_sel2[m]);

        float4 vk = *(const float4*)(f1 + (size_t)k * DD + tid * 4);
        float4 xa = *(const float4*)(f1 + (size_t)a * DD + tid * 4);
        float4 xb = *(const float4*)(f1 + (size_t)b * DD + tid * 4);
        float4 fm;
        fm.x = 0.5f * (xa.x + xb.x); fm.y = 0.5f * (xa.y + xb.y);
        fm.z = 0.5f * (xa.z + xb.z); fm.w = 0.5f * (xa.w + xb.w);
        float aa = vk.x * vk.x + vk.y * vk.y + vk.z * vk.z + vk.w * vk.w;
        float bb = fm.x * fm.x + fm.y * fm.y + fm.z * fm.z + fm.w * fm.w;
        float ab = vk.x * fm.x + vk.y * fm.y + vk.z * fm.z + vk.w * fm.w;

        // fold 3 sums into 2 shfl chains: (aa+bb) and ab, recover via d2 formula
        float s1 = aa + bb;
        #pragma unroll
        for (int o = 16; o; o >>= 1) {
            s1 += __shfl_xor_sync(0xffffffffu, s1, o);
            ab += __shfl_xor_sync(0xffffffffu, ab, o);
        }
        const int w = tid >> 5;
        if ((tid & 31) == 0) { red[w][0] = s1; red[w][1] = ab; }
        __syncthreads();
        if (tid == 0) {
            float t1 = 0.f, t2 = 0.f;
            #pragma unroll
            for (int q = 0; q < 16; q++) { t1 += red[q][0]; t2 += red[q][1]; }
            float d2 = t1 - 2.f * t2;
            float dan = sqrtf(fmaxf(d2, EPSF));
            g_trip[k] = __ldcg(&g_dist_ap[k]) - dan + MARGINF;
        }
    }

    // ================= finalize: last-arriving block (parallel) ============
    __threadfence();
    __syncthreads();
    if (tid == 0) {
        int done = atomicAdd(&g_c2, 1);
        s_last = (done == NBLK - 1) ? 1 : 0;
    }
    __syncthreads();
    if (s_last) {
        __threadfence();
        float t = (tid < NN) ? __ldcg(&g_trip[tid]) : 0.f;
        float v = (tid < NN && t > 0.f) ? t : 0.f;
        float c = (tid < NN && t > 0.f) ? 1.f : 0.f;
        #pragma unroll
        for (int o = 16; o; o >>= 1) {
            v += __shfl_xor_sync(0xffffffffu, v, o);
            c += __shfl_xor_sync(0xffffffffu, c, o);
        }
        const int w = tid >> 5;
        if ((tid & 31) == 0) { red[w][0] = v; red[w][1] = c; }
        __syncthreads();
        if (tid == 0) {
            float s = 0.f, cc = 0.f;
            #pragma unroll
            for (int q = 0; q < 4; q++) { s += red[q][0]; cc += red[q][1]; }
            out[0] = s * (1.0f / 128.0f);
            if (out_size > 1) out[1] = cc;
            // reset barriers for next graph replay
            g_c0 = 0; g_c1 = 0; g_c2 = 0;
        }
    }
}

// ---------------- launch ----------------
extern "C" void kernel_launch(void* const* d_in, const int* in_sizes, int n_in,
                              void* d_out, int out_size) {
    const float* f1 = (const float*)d_in[0];
    const float* f2 = (const float*)d_in[1];
    const int*   tgt = (const int*)d_in[2];
    (void)in_sizes; (void)n_in;

    k_fused<<<NBLK, 512>>>(f1, f2, tgt, (float*)d_out, out_size);
}

// round 6
// speedup vs baseline: 1.5850x; 1.5850x over previous
#include <cuda_runtime.h>
#include <math.h>
#include <stdint.h>

#define NN 128
#define DD 2048
#define EPSF 1e-12f
#define MARGINF 0.3f
#define KCHUNK 64        // K per GEMM block
#define KP 32            // k-pairs per chunk
#define NKCH 32          // K chunks (32*64 = 2048)
#define NBLK 128         // one block per SM, all co-resident
#define S2 66            // smem row stride in float2

// ---------------- device scratch (no allocations allowed) ----------------
__device__ float g_part[NN * NKCH * NN];   // partials [i][kc][j], 2 MB
__device__ float g_norm[2 * NN];
__device__ float g_dist_ap[NN];
__device__ int   g_sel1[NN];
__device__ int   g_sel2[NN];
__device__ float g_trip[NN];
__device__ int   g_c0, g_c1, g_c2;         // phase barriers (zero-init, self-reset)

__device__ __forceinline__ void ffma2(unsigned long long& acc,
                                      unsigned long long a, unsigned long long b) {
    asm("fma.rn.f32x2 %0, %1, %2, %0;" : "+l"(acc) : "l"(a), "l"(b));
}
__device__ __forceinline__ float2 up2(unsigned long long v) {
    float2 r;
    asm("mov.b64 {%0, %1}, %2;" : "=f"(r.x), "=f"(r.y) : "l"(v));
    return r;
}

// grid-wide spin barrier (all NBLK blocks resident)
__device__ __forceinline__ void gbar(int* c) {
    __threadfence();
    __syncthreads();
    if (threadIdx.x == 0) {
        atomicAdd(c, 1);
        while (*(volatile int*)c != NBLK) __nanosleep(32);
    }
    __syncthreads();
    __threadfence();
}

__global__ void __launch_bounds__(256, 1)
k_fused(const float* __restrict__ f1, const float* __restrict__ f2,
        const int* __restrict__ tgt, float* __restrict__ out, int out_size) {
    const int tid = threadIdx.x;
    const int bid = blockIdx.x;
    const int w = tid >> 5, lane = tid & 31;

    __shared__ float2 As2[KP][S2];   // As2[kp][row] = (A[2kp],A[2kp+1]) of row
    __shared__ float2 Bs2[KP][S2];
    __shared__ int    st[NN];
    __shared__ unsigned s_bal[4];
    __shared__ float  s_dot[2][NN];
    __shared__ float  nred[8];
    __shared__ float  s_ap[8];
    __shared__ unsigned long long s_k1[8], s_k2[8];
    __shared__ float  red[8][2];
    __shared__ int    s_last;

    // ================= Phase A: split-K GEMM + folded norms ================
    const int quad = bid >> 5;            // 0..3
    const int kc = bid & 31;
    const int i0 = (quad & 1) * 64;
    const int j0 = (quad >> 1) * 64;
    const int k0 = kc * KCHUNK;

    // GEMM tile loads: 64 rows x 64 K per matrix = 1024 float4; 4 per thread
    float4 va[4], vb[4];
    int rw[4], k4[4];
    #pragma unroll
    for (int s = 0; s < 4; s++) {
        const int idx = tid + 256 * s;    // 0..1023
        rw[s] = idx >> 4;                 // 0..63
        k4[s] = idx & 15;
        va[s] = *(const float4*)(f1 + (size_t)(i0 + rw[s]) * DD + k0 + k4[s] * 4);
        vb[s] = *(const float4*)(f2 + (size_t)(j0 + rw[s]) * DD + k0 + k4[s] * 4);
    }
    // norm rows 2*bid, 2*bid+1: 512 float4 per row, 4 per thread (coalesced)
    const int nrow = 2 * bid + (tid >> 7);
    const float4* nb = (const float4*)((nrow < NN) ? (f1 + (size_t)nrow * DD)
                                                   : (f2 + (size_t)(nrow - NN) * DD));
    float4 n0 = nb[(tid & 127)];
    float4 n1 = nb[(tid & 127) + 128];
    float4 n2 = nb[(tid & 127) + 256];
    float4 n3 = nb[(tid & 127) + 384];

    // stage GEMM tiles, k-pair interleaved
    #pragma unroll
    for (int s = 0; s < 4; s++) {
        As2[2 * k4[s] + 0][rw[s]] = make_float2(va[s].x, va[s].y);
        As2[2 * k4[s] + 1][rw[s]] = make_float2(va[s].z, va[s].w);
        Bs2[2 * k4[s] + 0][rw[s]] = make_float2(vb[s].x, vb[s].y);
        Bs2[2 * k4[s] + 1][rw[s]] = make_float2(vb[s].z, vb[s].w);
    }
    // norm partial (keeps only 1 live reg through GEMM)
    float ns = n0.x * n0.x + n0.y * n0.y + n0.z * n0.z + n0.w * n0.w
             + n1.x * n1.x + n1.y * n1.y + n1.z * n1.z + n1.w * n1.w
             + n2.x * n2.x + n2.y * n2.y + n2.z * n2.z + n2.w * n2.w
             + n3.x * n3.x + n3.y * n3.y + n3.z * n3.z + n3.w * n3.w;
    if (tid < NN) st[tid] = tgt[tid];
    __syncthreads();

    // 4x4 register tile; warp footprint = 4 (A) x 8 (B) distinct addresses
    const int ty4 = ((w >> 1) * 4 + (lane >> 3)) * 4;   // 16 row-groups
    const int tx4 = ((w & 1) * 8 + (lane & 7)) * 4;     // 16 col-groups

    unsigned long long acc[4][4];
    #pragma unroll
    for (int m = 0; m < 4; m++)
        #pragma unroll
        for (int n = 0; n < 4; n++) acc[m][n] = 0ull;

    #pragma unroll
    for (int kp = 0; kp < KP; kp++) {
        ulonglong2 a0 = *(const ulonglong2*)&As2[kp][ty4];
        ulonglong2 a1 = *(const ulonglong2*)&As2[kp][ty4 + 2];
        ulonglong2 b0 = *(const ulonglong2*)&Bs2[kp][tx4];
        ulonglong2 b1 = *(const ulonglong2*)&Bs2[kp][tx4 + 2];
        unsigned long long A[4] = {a0.x, a0.y, a1.x, a1.y};
        unsigned long long B[4] = {b0.x, b0.y, b1.x, b1.y};
        #pragma unroll
        for (int m = 0; m < 4; m++)
            #pragma unroll
            for (int n = 0; n < 4; n++)
                ffma2(acc[m][n], A[m], B[n]);
    }

    #pragma unroll
    for (int m = 0; m < 4; m++) {
        float v[4];
        #pragma unroll
        for (int n = 0; n < 4; n++) {
            float2 p = up2(acc[m][n]);
            v[n] = p.x + p.y;
        }
        *(float4*)&g_part[((size_t)(i0 + ty4 + m) * NKCH + kc) * NN + j0 + tx4] =
            make_float4(v[0], v[1], v[2], v[3]);
    }

    // norm reduce (each warp covers one row: tid>>7 constant within warp)
    #pragma unroll
    for (int o = 16; o; o >>= 1) ns += __shfl_xor_sync(0xffffffffu, ns, o);
    if (lane == 0) nred[w] = ns;

    // ballot-based rank among negatives (depends only on tgt)
    const int ti = st[bid];
    bool pos = false;
    unsigned mybal = 0;
    if (tid < NN) {
        pos = (st[tid] == ti);
        mybal = __ballot_sync(0xffffffffu, !pos);
        if (lane == 0) s_bal[w] = mybal;
    }
    __syncthreads();
    if (tid == 0)        g_norm[2 * bid]     = nred[0] + nred[1] + nred[2] + nred[3];
    else if (tid == 128) g_norm[2 * bid + 1] = nred[4] + nred[5] + nred[6] + nred[7];

    int rank = 0;
    if (tid < NN) {
        #pragma unroll
        for (int q = 0; q < 4; q++) rank += (q < w) ? __popc(s_bal[q]) : 0;
        rank += __popc(mybal & ((1u << lane) - 1u));
    }

    gbar(&g_c0);

    // ================= Phase B: distances + hard-example selection ========
    {
        const int i = bid;
        const int j = tid & 127;
        const int kh = tid >> 7;           // 2 K-halves of 16 chunks each

        const float* pp = g_part + ((size_t)i * NKCH + kh * 16) * NN + j;
        float a0 = 0.f, a1 = 0.f, a2 = 0.f, a3 = 0.f;
        #pragma unroll
        for (int c = 0; c < 16; c += 4) {
            a0 += __ldcg(pp + (size_t)(c + 0) * NN);
            a1 += __ldcg(pp + (size_t)(c + 1) * NN);
            a2 += __ldcg(pp + (size_t)(c + 2) * NN);
            a3 += __ldcg(pp + (size_t)(c + 3) * NN);
        }
        s_dot[kh][j] = (a0 + a1) + (a2 + a3);
        __syncthreads();

        if (tid < NN) {
            float dot = s_dot[0][j] + s_dot[1][j];
            float d2 = __ldcg(&g_norm[i]) + __ldcg(&g_norm[NN + j]) - 2.f * dot;
            float d = sqrtf(fmaxf(d2, EPSF));

            float apv = pos ? d : -INFINITY;
            // (distance, column) lexicographic key: min == argmin with
            // first-occurrence tie-break (d > 0, float bits order-preserving)
            unsigned long long key =
                ((unsigned long long)__float_as_uint(d) << 32) | (unsigned)j;
            unsigned long long k1 = (!pos && rank < 56) ? key : ~0ull;
            unsigned long long k2 = (!pos && rank >= 56 && rank < 112) ? key : ~0ull;

            #pragma unroll
            for (int o = 16; o; o >>= 1) {
                apv = fmaxf(apv, __shfl_xor_sync(0xffffffffu, apv, o));
                unsigned long long t1 = __shfl_xor_sync(0xffffffffu, k1, o);
                unsigned long long t2 = __shfl_xor_sync(0xffffffffu, k2, o);
                k1 = (t1 < k1) ? t1 : k1;
                k2 = (t2 < k2) ? t2 : k2;
            }
            if (lane == 0) { s_ap[w] = apv; s_k1[w] = k1; s_k2[w] = k2; }
        }
        __syncthreads();
        if (tid == 0) {
            float ap = s_ap[0];
            unsigned long long m1 = s_k1[0], m2 = s_k2[0];
            #pragma unroll
            for (int q = 1; q < 4; q++) {
                ap = fmaxf(ap, s_ap[q]);
                if (s_k1[q] < m1) m1 = s_k1[q];
                if (s_k2[q] < m2) m2 = s_k2[q];
            }
            g_dist_ap[i] = ap;
            g_sel1[i] = (int)(m1 & 0xffffffffull);
            g_sel2[i] = (int)(m2 & 0xffffffffull);
        }
    }

    gbar(&g_c1);

    // ================= Phase C: dist_an + triplet ==========================
    {
        const int k = bid;
        // feat_rgb_mid / feat_ir_mid index shuffle; anchor is always f1[k]
        int m = (k < 32) ? k : (k < 64) ? (k + 32) : (k < 96) ? (k - 32) : k;
        const int a = __ldcg(&g_sel1[m]);
        const int b = __ldcg(&g_sel2[m]);

        const float4* xk = (const float4*)(f1 + (size_t)k * DD);
        const float4* xa = (const float4*)(f1 + (size_t)a * DD);
        const float4* xb = (const float4*)(f1 + (size_t)b * DD);

        float s1 = 0.f, ab = 0.f;
        #pragma unroll
        for (int s = 0; s < 2; s++) {
            const int t = tid + 256 * s;
            float4 vk = xk[t], v1 = xa[t], v2 = xb[t];
            float4 fm;
            fm.x = 0.5f * (v1.x + v2.x); fm.y = 0.5f * (v1.y + v2.y);
            fm.z = 0.5f * (v1.z + v2.z); fm.w = 0.5f * (v1.w + v2.w);
            s1 += vk.x * vk.x + vk.y * vk.y + vk.z * vk.z + vk.w * vk.w
                + fm.x * fm.x + fm.y * fm.y + fm.z * fm.z + fm.w * fm.w;
            ab += vk.x * fm.x + vk.y * fm.y + vk.z * fm.z + vk.w * fm.w;
        }
        #pragma unroll
        for (int o = 16; o; o >>= 1) {
            s1 += __shfl_xor_sync(0xffffffffu, s1, o);
            ab += __shfl_xor_sync(0xffffffffu, ab, o);
        }
        if (lane == 0) { red[w][0] = s1; red[w][1] = ab; }
        __syncthreads();
        if (tid == 0) {
            float t1 = 0.f, t2 = 0.f;
            #pragma unroll
            for (int q = 0; q < 8; q++) { t1 += red[q][0]; t2 += red[q][1]; }
            float d2 = t1 - 2.f * t2;
            float dan = sqrtf(fmaxf(d2, EPSF));
            g_trip[k] = __ldcg(&g_dist_ap[k]) - dan + MARGINF;
        }
    }

    // ================= finalize: last-arriving block (parallel) ============
    __threadfence();
    __syncthreads();
    if (tid == 0) {
        int done = atomicAdd(&g_c2, 1);
        s_last = (done == NBLK - 1) ? 1 : 0;
    }
    __syncthreads();
    if (s_last) {
        __threadfence();
        float t = (tid < NN) ? __ldcg(&g_trip[tid]) : 0.f;
        float v = (tid < NN && t > 0.f) ? t : 0.f;
        float c = (tid < NN && t > 0.f) ? 1.f : 0.f;
        #pragma unroll
        for (int o = 16; o; o >>= 1) {
            v += __shfl_xor_sync(0xffffffffu, v, o);
            c += __shfl_xor_sync(0xffffffffu, c, o);
        }
        if (lane == 0) { red[w][0] = v; red[w][1] = c; }
        __syncthreads();
        if (tid == 0) {
            float s = 0.f, cc = 0.f;
            #pragma unroll
            for (int q = 0; q < 4; q++) { s += red[q][0]; cc += red[q][1]; }
            out[0] = s * (1.0f / 128.0f);
            if (out_size > 1) out[1] = cc;
            // reset barriers for next graph replay
            g_c0 = 0; g_c1 = 0; g_c2 = 0;
        }
    }
}

// ---------------- launch ----------------
extern "C" void kernel_launch(void* const* d_in, const int* in_sizes, int n_in,
                              void* d_out, int out_size) {
    const float* f1 = (const float*)d_in[0];
    const float* f2 = (const float*)d_in[1];
    const int*   tgt = (const int*)d_in[2];
    (void)in_sizes; (void)n_in;

    k_fused<<<NBLK, 256>>>(f1, f2, tgt, (float*)d_out, out_size);
}